// round 2
// baseline (speedup 1.0000x reference)
#include <cuda_runtime.h>
#include <cuda_bf16.h>

// VGAE encoder: 4 GCN layers (shared normalization), N~100k nodes, E~1.6M edges, C=32.
// Per layer: GEMM (h = relu?(x) @ W) -> init (out = h*deg_inv + b) -> edge scatter
// (out[dst] += h[src]*norm via red.global.add.v4.f32).

#define N_MAX 131072
#define E_MAX 2097152

// Scratch (device globals; no allocations allowed)
__device__ int   g_is64;
__device__ float g_deg[N_MAX];
__device__ float g_dis[N_MAX];
__device__ int   g_src[E_MAX];
__device__ int   g_dst[E_MAX];
__device__ float g_norm[E_MAX];
__device__ float g_bufA[(size_t)N_MAX * 32];
__device__ float g_bufB[(size_t)N_MAX * 32];
__device__ float g_bufC[(size_t)N_MAX * 32];

// ---------------------------------------------------------------------------
// Edge dtype detection: if edge_index is int64 (values < N ~ 1e5), every odd
// int32 word (high half) is 0. If int32, odd words are random src indices.
// ---------------------------------------------------------------------------

__global__ void k_detect(const int* __restrict__ ei32, int E) {
    if (threadIdx.x != 0 || blockIdx.x != 0) return;
    int n_check = 512;
    if (2 * n_check > 2 * E) n_check = E;
    int allzero = 1;
    for (int k = 0; k < n_check; k++) {
        if (ei32[2 * k + 1] != 0) { allzero = 0; break; }
    }
    g_is64 = allzero;
}

__global__ void k_deg_init(int n) {
    int i = blockIdx.x * blockDim.x + threadIdx.x;
    if (i < n) g_deg[i] = 1.0f;  // self-loop
}

__global__ void k_edge_prep(const void* __restrict__ eiv, int E) {
    int e = blockIdx.x * blockDim.x + threadIdx.x;
    if (e >= E) return;
    int s, d;
    if (g_is64) {
        const long long* ei = (const long long*)eiv;
        s = (int)ei[e];
        d = (int)ei[(size_t)E + e];
    } else {
        const int* ei = (const int*)eiv;
        s = ei[e];
        d = ei[(size_t)E + e];
    }
    g_src[e] = s;
    g_dst[e] = d;
    atomicAdd(&g_deg[d], 1.0f);
}

__global__ void k_dis(int n) {
    int i = blockIdx.x * blockDim.x + threadIdx.x;
    if (i < n) g_dis[i] = rsqrtf(g_deg[i]);
}

__global__ void k_norm(int E) {
    int e = blockIdx.x * blockDim.x + threadIdx.x;
    if (e < E) g_norm[e] = g_dis[g_src[e]] * g_dis[g_dst[e]];
}

// ---------------------------------------------------------------------------
// Dense GEMM: out[n,32] = relu?(in[n,32]) @ W[32,32]
// One thread per row; W broadcast from smem.
// ---------------------------------------------------------------------------

__global__ __launch_bounds__(256) void k_gemm(
    const float* __restrict__ in, const float* __restrict__ W,
    float* __restrict__ out, int n, int relu_in)
{
    __shared__ float4 sW[256];  // 32 rows x 8 float4
    sW[threadIdx.x] = ((const float4*)W)[threadIdx.x];
    __syncthreads();

    int r = blockIdx.x * blockDim.x + threadIdx.x;
    if (r >= n) return;

    const float4* inr = (const float4*)(in + (size_t)r * 32);
    float xk[32];
#pragma unroll
    for (int i = 0; i < 8; i++) {
        float4 v = inr[i];
        if (relu_in) {
            v.x = fmaxf(v.x, 0.0f); v.y = fmaxf(v.y, 0.0f);
            v.z = fmaxf(v.z, 0.0f); v.w = fmaxf(v.w, 0.0f);
        }
        xk[4 * i + 0] = v.x; xk[4 * i + 1] = v.y;
        xk[4 * i + 2] = v.z; xk[4 * i + 3] = v.w;
    }

    float4 acc[8];
#pragma unroll
    for (int j = 0; j < 8; j++) acc[j] = make_float4(0.f, 0.f, 0.f, 0.f);

#pragma unroll
    for (int k = 0; k < 32; k++) {
        float a = xk[k];
#pragma unroll
        for (int j = 0; j < 8; j++) {
            float4 w = sW[k * 8 + j];
            acc[j].x += a * w.x; acc[j].y += a * w.y;
            acc[j].z += a * w.z; acc[j].w += a * w.w;
        }
    }

    float4* outr = (float4*)(out + (size_t)r * 32);
#pragma unroll
    for (int j = 0; j < 8; j++) outr[j] = acc[j];
}

// ---------------------------------------------------------------------------
// Self-loop + bias init: out[i,:] = h[i,:] * dis[i]^2 + b
// ---------------------------------------------------------------------------

__global__ void k_init(const float* __restrict__ h, const float* __restrict__ b,
                       float* __restrict__ out, int n)
{
    int i = blockIdx.x * blockDim.x + threadIdx.x;
    if (i >= n * 8) return;
    int node = i >> 3;
    int c = i & 7;
    float s = g_dis[node]; s *= s;
    float4 hv = ((const float4*)h)[i];
    float4 bv = ((const float4*)b)[c];
    float4 o;
    o.x = hv.x * s + bv.x; o.y = hv.y * s + bv.y;
    o.z = hv.z * s + bv.z; o.w = hv.w * s + bv.w;
    ((float4*)out)[i] = o;
}

// ---------------------------------------------------------------------------
// Edge scatter: out[dst,:] += h[src,:] * norm  (8 threads per edge, float4 each)
// ---------------------------------------------------------------------------

__device__ __forceinline__ void red_add_v4(float* p, float4 v) {
    asm volatile("red.global.add.v4.f32 [%0], {%1, %2, %3, %4};"
                 :: "l"(p), "f"(v.x), "f"(v.y), "f"(v.z), "f"(v.w)
                 : "memory");
}

__global__ void k_scatter(const float* __restrict__ h, float* __restrict__ out, int E)
{
    long long t = (long long)blockIdx.x * blockDim.x + threadIdx.x;
    if (t >= (long long)E * 8) return;
    int e = (int)(t >> 3);
    int q = (int)(t & 7);
    int s = g_src[e];
    int d = g_dst[e];
    float w = g_norm[e];
    float4 v = ((const float4*)h)[(size_t)s * 8 + q];
    v.x *= w; v.y *= w; v.z *= w; v.w *= w;
    red_add_v4(out + (size_t)d * 32 + q * 4, v);
}

// Dual scatter for mu / logvar (shares index + norm loads)
__global__ void k_scatter2(const float* __restrict__ ha, const float* __restrict__ hb,
                           float* __restrict__ oa, float* __restrict__ ob, int E)
{
    long long t = (long long)blockIdx.x * blockDim.x + threadIdx.x;
    if (t >= (long long)E * 8) return;
    int e = (int)(t >> 3);
    int q = (int)(t & 7);
    int s = g_src[e];
    int d = g_dst[e];
    float w = g_norm[e];
    size_t goff = (size_t)s * 8 + q;
    float4 va = ((const float4*)ha)[goff];
    float4 vb = ((const float4*)hb)[goff];
    va.x *= w; va.y *= w; va.z *= w; va.w *= w;
    vb.x *= w; vb.y *= w; vb.z *= w; vb.w *= w;
    size_t soff = (size_t)d * 32 + q * 4;
    red_add_v4(oa + soff, va);
    red_add_v4(ob + soff, vb);
}

// ---------------------------------------------------------------------------
// Launch
// ---------------------------------------------------------------------------

static inline int cdiv(long long a, int b) { return (int)((a + b - 1) / b); }

extern "C" void kernel_launch(void* const* d_in, const int* in_sizes, int n_in,
                              void* d_out, int out_size)
{
    const float* x   = (const float*)d_in[0];
    const void*  ei  = d_in[1];
    const float* W1  = (const float*)d_in[2];
    const float* b1  = (const float*)d_in[3];
    const float* W2  = (const float*)d_in[4];
    const float* b2  = (const float*)d_in[5];
    const float* Wmu = (const float*)d_in[6];
    const float* bmu = (const float*)d_in[7];
    const float* Wlv = (const float*)d_in[8];
    const float* blv = (const float*)d_in[9];

    int N = in_sizes[0] / 32;
    int E = in_sizes[1] / 2;

    float* mu = (float*)d_out;
    float* lv = mu + (size_t)N * 32;

    float* bufA; float* bufB; float* bufC;
    cudaGetSymbolAddress((void**)&bufA, g_bufA);
    cudaGetSymbolAddress((void**)&bufB, g_bufB);
    cudaGetSymbolAddress((void**)&bufC, g_bufC);

    const int T = 256;
    int gN  = cdiv(N, T);                 // per-node
    int gN8 = cdiv((long long)N * 8, T);  // per-float4
    int gE  = cdiv(E, T);                 // per-edge
    int gE8 = cdiv((long long)E * 8, T);  // per-edge-quad

    // Normalization prep
    k_detect<<<1, 32>>>((const int*)ei, E);
    k_deg_init<<<gN, T>>>(N);
    k_edge_prep<<<gE, T>>>(ei, E);
    k_dis<<<gN, T>>>(N);
    k_norm<<<gE, T>>>(E);

    // Layer 1: h = x @ W1; a = scatter(h) + b1
    k_gemm<<<gN, T>>>(x, W1, bufA, N, 0);
    k_init<<<gN8, T>>>(bufA, b1, bufB, N);
    k_scatter<<<gE8, T>>>(bufA, bufB, E);

    // Layer 2: h = relu(a) @ W2; a = scatter(h) + b2
    k_gemm<<<gN, T>>>(bufB, W2, bufA, N, 1);
    k_init<<<gN8, T>>>(bufA, b2, bufB, N);
    k_scatter<<<gE8, T>>>(bufA, bufB, E);

    // Heads: hmu = relu(a) @ Wmu; hlv = relu(a) @ Wlv; dual scatter
    k_gemm<<<gN, T>>>(bufB, Wmu, bufA, N, 1);
    k_gemm<<<gN, T>>>(bufB, Wlv, bufC, N, 1);
    k_init<<<gN8, T>>>(bufA, bmu, mu, N);
    k_init<<<gN8, T>>>(bufC, blv, lv, N);
    k_scatter2<<<gE8, T>>>(bufA, bufC, mu, lv, E);
}

// round 3
// speedup vs baseline: 1.1497x; 1.1497x over previous
#include <cuda_runtime.h>
#include <cuda_bf16.h>

// VGAE encoder, pull-based: build CSR (dst-grouped adjacency) once per call,
// then each GCN layer = GEMM (h = relu?(x) @ W) + warp-per-node gather-aggregate
// (out[i] = sum_j w_ij * h[src_j] + dis_i^2 * h[i] + b). No scatter atomics.

#define N_MAX 131072
#define E_MAX 2097152
#define NB_MAX 512  // max blocks in the node-count scan (N_MAX/256 = 512)

// Scratch (device globals; no allocations allowed)
__device__ int   g_is64;
__device__ int   g_cnt[N_MAX];       // in-degree (excluding self-loop)
__device__ int   g_rowstart[N_MAX];
__device__ int   g_cur[N_MAX];       // permutation cursor
__device__ float g_dis[N_MAX];       // deg^-1/2 (deg includes self-loop)
__device__ int   g_src[E_MAX];
__device__ int   g_dst[E_MAX];
__device__ int2  g_adj[E_MAX];       // CSR payload: (src, __float_as_int(norm))
__device__ int   g_bsum[NB_MAX];
__device__ int   g_boff[NB_MAX];
__device__ float g_bufA[(size_t)N_MAX * 32];
__device__ float g_bufB[(size_t)N_MAX * 32];
__device__ float g_bufC[(size_t)N_MAX * 32];

// ---------------------------------------------------------------------------
// Edge dtype detection: if edge_index is int64 (values < N ~ 1e5), every odd
// int32 word (high half) is 0. If int32, odd words are random src indices.
// ---------------------------------------------------------------------------

__global__ void k_detect(const int* __restrict__ ei32, int E) {
    if (threadIdx.x != 0 || blockIdx.x != 0) return;
    int n_check = 512;
    if (n_check > E) n_check = E;
    int allzero = 1;
    for (int k = 0; k < n_check; k++) {
        if (ei32[2 * k + 1] != 0) { allzero = 0; break; }
    }
    g_is64 = allzero;
}

__global__ void k_zero_cnt(int n) {
    int i = blockIdx.x * blockDim.x + threadIdx.x;
    if (i < n) g_cnt[i] = 0;
}

__global__ void k_edge_prep(const void* __restrict__ eiv, int E) {
    int e = blockIdx.x * blockDim.x + threadIdx.x;
    if (e >= E) return;
    int s, d;
    if (g_is64) {
        const long long* ei = (const long long*)eiv;
        s = (int)ei[e];
        d = (int)ei[(size_t)E + e];
    } else {
        const int* ei = (const int*)eiv;
        s = ei[e];
        d = ei[(size_t)E + e];
    }
    g_src[e] = s;
    g_dst[e] = d;
    atomicAdd(&g_cnt[d], 1);
}

// --- two-level exclusive scan of g_cnt -> g_rowstart -------------------------

__global__ __launch_bounds__(256) void k_blocksum(int n) {
    __shared__ int sm[256];
    int t = threadIdx.x;
    int i = blockIdx.x * 256 + t;
    sm[t] = (i < n) ? g_cnt[i] : 0;
    __syncthreads();
#pragma unroll
    for (int off = 128; off > 0; off >>= 1) {
        if (t < off) sm[t] += sm[t + off];
        __syncthreads();
    }
    if (t == 0) g_bsum[blockIdx.x] = sm[0];
}

__global__ __launch_bounds__(NB_MAX) void k_scan_bsum(int nb) {
    __shared__ int s[NB_MAX];
    int t = threadIdx.x;
    int v = (t < nb) ? g_bsum[t] : 0;
    s[t] = v;
    __syncthreads();
#pragma unroll
    for (int off = 1; off < NB_MAX; off <<= 1) {
        int a = (t >= off) ? s[t - off] : 0;
        __syncthreads();
        s[t] += a;
        __syncthreads();
    }
    if (t < nb) g_boff[t] = s[t] - v;  // exclusive
}

__global__ __launch_bounds__(256) void k_rowstart(int n) {
    __shared__ int s[256];
    int t = threadIdx.x;
    int i = blockIdx.x * 256 + t;
    int v = (i < n) ? g_cnt[i] : 0;
    s[t] = v;
    __syncthreads();
#pragma unroll
    for (int off = 1; off < 256; off <<= 1) {
        int a = (t >= off) ? s[t - off] : 0;
        __syncthreads();
        s[t] += a;
        __syncthreads();
    }
    if (i < n) {
        int rs = g_boff[blockIdx.x] + s[t] - v;
        g_rowstart[i] = rs;
        g_cur[i] = rs;
        g_dis[i] = rsqrtf((float)(v + 1));  // +1 self-loop
    }
}

__global__ void k_permute(int E) {
    int e = blockIdx.x * blockDim.x + threadIdx.x;
    if (e >= E) return;
    int s = g_src[e];
    int d = g_dst[e];
    int pos = atomicAdd(&g_cur[d], 1);
    int2 ev;
    ev.x = s;
    ev.y = __float_as_int(g_dis[s] * g_dis[d]);
    g_adj[pos] = ev;
}

// ---------------------------------------------------------------------------
// Dense GEMM: out[n,32] = relu?(in[n,32]) @ W[32,32]
// One thread per row; W broadcast from smem.
// ---------------------------------------------------------------------------

__global__ __launch_bounds__(256) void k_gemm(
    const float* __restrict__ in, const float* __restrict__ W,
    float* __restrict__ out, int n, int relu_in)
{
    __shared__ float4 sW[256];  // 32 rows x 8 float4
    sW[threadIdx.x] = ((const float4*)W)[threadIdx.x];
    __syncthreads();

    int r = blockIdx.x * blockDim.x + threadIdx.x;
    if (r >= n) return;

    const float4* inr = (const float4*)(in + (size_t)r * 32);
    float xk[32];
#pragma unroll
    for (int i = 0; i < 8; i++) {
        float4 v = inr[i];
        if (relu_in) {
            v.x = fmaxf(v.x, 0.0f); v.y = fmaxf(v.y, 0.0f);
            v.z = fmaxf(v.z, 0.0f); v.w = fmaxf(v.w, 0.0f);
        }
        xk[4 * i + 0] = v.x; xk[4 * i + 1] = v.y;
        xk[4 * i + 2] = v.z; xk[4 * i + 3] = v.w;
    }

    float4 acc[8];
#pragma unroll
    for (int j = 0; j < 8; j++) acc[j] = make_float4(0.f, 0.f, 0.f, 0.f);

#pragma unroll
    for (int k = 0; k < 32; k++) {
        float a = xk[k];
#pragma unroll
        for (int j = 0; j < 8; j++) {
            float4 w = sW[k * 8 + j];
            acc[j].x += a * w.x; acc[j].y += a * w.y;
            acc[j].z += a * w.z; acc[j].w += a * w.w;
        }
    }

    float4* outr = (float4*)(out + (size_t)r * 32);
#pragma unroll
    for (int j = 0; j < 8; j++) outr[j] = acc[j];
}

// ---------------------------------------------------------------------------
// Gather-aggregate: one warp per node, lane = channel.
// out[i,lane] = dis_i^2 * h[i,lane] + sum_j norm_j * h[src_j,lane] + b[lane]
// ---------------------------------------------------------------------------

__global__ __launch_bounds__(256) void k_agg(
    const float* __restrict__ h, const float* __restrict__ b,
    float* __restrict__ out, int n)
{
    int warp = (blockIdx.x * blockDim.x + threadIdx.x) >> 5;
    int lane = threadIdx.x & 31;
    if (warp >= n) return;

    int rs = g_rowstart[warp];
    int cnt = g_cnt[warp];
    float dis = g_dis[warp];

    float acc = dis * dis * h[(size_t)warp * 32 + lane];

    int j = rs, end = rs + cnt;
    for (; j + 4 <= end; j += 4) {
        int2 e0 = g_adj[j + 0];
        int2 e1 = g_adj[j + 1];
        int2 e2 = g_adj[j + 2];
        int2 e3 = g_adj[j + 3];
        float v0 = h[(size_t)e0.x * 32 + lane];
        float v1 = h[(size_t)e1.x * 32 + lane];
        float v2 = h[(size_t)e2.x * 32 + lane];
        float v3 = h[(size_t)e3.x * 32 + lane];
        acc += __int_as_float(e0.y) * v0;
        acc += __int_as_float(e1.y) * v1;
        acc += __int_as_float(e2.y) * v2;
        acc += __int_as_float(e3.y) * v3;
    }
    for (; j < end; j++) {
        int2 ev = g_adj[j];
        acc += __int_as_float(ev.y) * h[(size_t)ev.x * 32 + lane];
    }

    out[(size_t)warp * 32 + lane] = acc + b[lane];
}

// Dual aggregate for mu/logvar (shares adjacency loads)
__global__ __launch_bounds__(256) void k_agg2(
    const float* __restrict__ ha, const float* __restrict__ hb,
    const float* __restrict__ ba, const float* __restrict__ bb,
    float* __restrict__ oa, float* __restrict__ ob, int n)
{
    int warp = (blockIdx.x * blockDim.x + threadIdx.x) >> 5;
    int lane = threadIdx.x & 31;
    if (warp >= n) return;

    int rs = g_rowstart[warp];
    int cnt = g_cnt[warp];
    float dis = g_dis[warp];

    size_t self = (size_t)warp * 32 + lane;
    float acca = dis * dis * ha[self];
    float accb = dis * dis * hb[self];

    int j = rs, end = rs + cnt;
    for (; j + 2 <= end; j += 2) {
        int2 e0 = g_adj[j + 0];
        int2 e1 = g_adj[j + 1];
        size_t o0 = (size_t)e0.x * 32 + lane;
        size_t o1 = (size_t)e1.x * 32 + lane;
        float a0 = ha[o0], b0 = hb[o0];
        float a1 = ha[o1], b1 = hb[o1];
        float w0 = __int_as_float(e0.y);
        float w1 = __int_as_float(e1.y);
        acca += w0 * a0 + w1 * a1;
        accb += w0 * b0 + w1 * b1;
    }
    for (; j < end; j++) {
        int2 ev = g_adj[j];
        size_t o = (size_t)ev.x * 32 + lane;
        float w = __int_as_float(ev.y);
        acca += w * ha[o];
        accb += w * hb[o];
    }

    oa[self] = acca + ba[lane];
    ob[self] = accb + bb[lane];
}

// ---------------------------------------------------------------------------
// Launch
// ---------------------------------------------------------------------------

static inline int cdiv(long long a, int b) { return (int)((a + b - 1) / b); }

extern "C" void kernel_launch(void* const* d_in, const int* in_sizes, int n_in,
                              void* d_out, int out_size)
{
    const float* x   = (const float*)d_in[0];
    const void*  ei  = d_in[1];
    const float* W1  = (const float*)d_in[2];
    const float* b1  = (const float*)d_in[3];
    const float* W2  = (const float*)d_in[4];
    const float* b2  = (const float*)d_in[5];
    const float* Wmu = (const float*)d_in[6];
    const float* bmu = (const float*)d_in[7];
    const float* Wlv = (const float*)d_in[8];
    const float* blv = (const float*)d_in[9];

    int N = in_sizes[0] / 32;
    int E = in_sizes[1] / 2;

    float* mu = (float*)d_out;
    float* lv = mu + (size_t)N * 32;

    float* bufA; float* bufB; float* bufC;
    cudaGetSymbolAddress((void**)&bufA, g_bufA);
    cudaGetSymbolAddress((void**)&bufB, g_bufB);
    cudaGetSymbolAddress((void**)&bufC, g_bufC);

    const int T = 256;
    int gN  = cdiv(N, T);                  // per-node
    int gE  = cdiv(E, T);                  // per-edge
    int gW  = cdiv((long long)N * 32, T);  // warp-per-node

    // CSR build
    k_detect<<<1, 32>>>((const int*)ei, E);
    k_zero_cnt<<<gN, T>>>(N);
    k_edge_prep<<<gE, T>>>(ei, E);
    k_blocksum<<<gN, T>>>(N);
    k_scan_bsum<<<1, NB_MAX>>>(gN);
    k_rowstart<<<gN, T>>>(N);
    k_permute<<<gE, T>>>(E);

    // Layer 1: h = x @ W1; a1 = A_hat h + b1
    k_gemm<<<gN, T>>>(x, W1, bufA, N, 0);
    k_agg<<<gW, T>>>(bufA, b1, bufB, N);

    // Layer 2: h = relu(a1) @ W2; a2 = A_hat h + b2
    k_gemm<<<gN, T>>>(bufB, W2, bufA, N, 1);
    k_agg<<<gW, T>>>(bufA, b2, bufB, N);

    // Heads: hmu = relu(a2) @ Wmu; hlv = relu(a2) @ Wlv; dual aggregate
    k_gemm<<<gN, T>>>(bufB, Wmu, bufA, N, 1);
    k_gemm<<<gN, T>>>(bufB, Wlv, bufC, N, 1);
    k_agg2<<<gW, T>>>(bufA, bufC, bmu, blv, mu, lv, N);
}

// round 4
// speedup vs baseline: 1.2367x; 1.0757x over previous
#include <cuda_runtime.h>
#include <cuda_bf16.h>

// VGAE encoder, pull-based: build CSR (dst-grouped adjacency) once per call,
// then each GCN layer = GEMM (h = relu?(x) @ W) + warp-per-node gather-aggregate
// (out[i] = sum_j w_ij * h[src_j] + dis_i^2 * h[i] + b). No scatter atomics.

#define N_MAX 131072
#define E_MAX 2097152

// Scratch (device globals; no allocations allowed)
__device__ int   g_is64;
__device__ int   g_alloc;            // CSR region allocator
__device__ int   g_cnt[N_MAX];       // in-degree (excluding self-loop)
__device__ int   g_rowstart[N_MAX];
__device__ int   g_cur[N_MAX];       // permutation cursor
__device__ float g_dis[N_MAX];       // deg^-1/2 (deg includes self-loop)
__device__ int   g_src[E_MAX];
__device__ int   g_dst[E_MAX];
__device__ int2  g_adj[E_MAX];       // CSR payload: (src, __float_as_int(norm))
__device__ float g_bufA[(size_t)N_MAX * 32];
__device__ float g_bufB[(size_t)N_MAX * 32];
__device__ float g_bufC[(size_t)N_MAX * 32];

// ---------------------------------------------------------------------------
// Edge dtype detection (parallel): if edge_index is int64 (values < N ~ 1e5),
// every odd int32 word (high half) is 0. If int32, odd words are random src
// indices and are essentially never all zero across 512 samples.
// ---------------------------------------------------------------------------

__global__ __launch_bounds__(512) void k_detect(const int* __restrict__ ei32, int E) {
    int n_check = 512 < E ? 512 : E;
    int t = threadIdx.x;
    int nz = (t < n_check && ei32[2 * t + 1] != 0) ? 1 : 0;
    int any = __syncthreads_or(nz);
    if (t == 0) {
        g_is64 = !any;
        g_alloc = 0;
    }
}

__global__ void k_zero_cnt(int n) {
    int i = blockIdx.x * blockDim.x + threadIdx.x;
    if (i < n) g_cnt[i] = 0;
}

__global__ void k_edge_prep(const void* __restrict__ eiv, int E) {
    int e = blockIdx.x * blockDim.x + threadIdx.x;
    if (e >= E) return;
    int s, d;
    if (g_is64) {
        const long long* ei = (const long long*)eiv;
        s = (int)ei[e];
        d = (int)ei[(size_t)E + e];
    } else {
        const int* ei = (const int*)eiv;
        s = ei[e];
        d = ei[(size_t)E + e];
    }
    g_src[e] = s;
    g_dst[e] = d;
    atomicAdd(&g_cnt[d], 1);
}

// Atomic CSR region allocation: each node grabs a contiguous [rs, rs+cnt)
// slice of g_adj. Segment ordering across nodes is arbitrary — irrelevant
// for the warp-per-node gather, which streams its own segment.
__global__ void k_rowalloc(int n) {
    int i = blockIdx.x * blockDim.x + threadIdx.x;
    if (i >= n) return;
    int c = g_cnt[i];
    int rs = atomicAdd(&g_alloc, c);
    g_rowstart[i] = rs;
    g_cur[i] = rs;
    g_dis[i] = rsqrtf((float)(c + 1));  // +1 self-loop
}

__global__ void k_permute(int E) {
    int e = blockIdx.x * blockDim.x + threadIdx.x;
    if (e >= E) return;
    int s = g_src[e];
    int d = g_dst[e];
    int pos = atomicAdd(&g_cur[d], 1);
    int2 ev;
    ev.x = s;
    ev.y = __float_as_int(g_dis[s] * g_dis[d]);
    g_adj[pos] = ev;
}

// ---------------------------------------------------------------------------
// Dense GEMM: out[n,32] = relu?(in[n,32]) @ W[32,32]
// One thread per row; W broadcast from smem.
// ---------------------------------------------------------------------------

__global__ __launch_bounds__(256) void k_gemm(
    const float* __restrict__ in, const float* __restrict__ W,
    float* __restrict__ out, int n, int relu_in)
{
    __shared__ float4 sW[256];  // 32 rows x 8 float4
    sW[threadIdx.x] = ((const float4*)W)[threadIdx.x];
    __syncthreads();

    int r = blockIdx.x * blockDim.x + threadIdx.x;
    if (r >= n) return;

    const float4* inr = (const float4*)(in + (size_t)r * 32);
    float xk[32];
#pragma unroll
    for (int i = 0; i < 8; i++) {
        float4 v = inr[i];
        if (relu_in) {
            v.x = fmaxf(v.x, 0.0f); v.y = fmaxf(v.y, 0.0f);
            v.z = fmaxf(v.z, 0.0f); v.w = fmaxf(v.w, 0.0f);
        }
        xk[4 * i + 0] = v.x; xk[4 * i + 1] = v.y;
        xk[4 * i + 2] = v.z; xk[4 * i + 3] = v.w;
    }

    float4 acc[8];
#pragma unroll
    for (int j = 0; j < 8; j++) acc[j] = make_float4(0.f, 0.f, 0.f, 0.f);

#pragma unroll
    for (int k = 0; k < 32; k++) {
        float a = xk[k];
#pragma unroll
        for (int j = 0; j < 8; j++) {
            float4 w = sW[k * 8 + j];
            acc[j].x += a * w.x; acc[j].y += a * w.y;
            acc[j].z += a * w.z; acc[j].w += a * w.w;
        }
    }

    float4* outr = (float4*)(out + (size_t)r * 32);
#pragma unroll
    for (int j = 0; j < 8; j++) outr[j] = acc[j];
}

// Dual GEMM (always relu input): two weight matrices, one input read.
__global__ __launch_bounds__(256) void k_gemm2(
    const float* __restrict__ in,
    const float* __restrict__ Wa, const float* __restrict__ Wb,
    float* __restrict__ oa, float* __restrict__ ob, int n)
{
    __shared__ float4 sWa[256];
    __shared__ float4 sWb[256];
    sWa[threadIdx.x] = ((const float4*)Wa)[threadIdx.x];
    sWb[threadIdx.x] = ((const float4*)Wb)[threadIdx.x];
    __syncthreads();

    int r = blockIdx.x * blockDim.x + threadIdx.x;
    if (r >= n) return;

    const float4* inr = (const float4*)(in + (size_t)r * 32);
    float xk[32];
#pragma unroll
    for (int i = 0; i < 8; i++) {
        float4 v = inr[i];
        v.x = fmaxf(v.x, 0.0f); v.y = fmaxf(v.y, 0.0f);
        v.z = fmaxf(v.z, 0.0f); v.w = fmaxf(v.w, 0.0f);
        xk[4 * i + 0] = v.x; xk[4 * i + 1] = v.y;
        xk[4 * i + 2] = v.z; xk[4 * i + 3] = v.w;
    }

    float4 acca[8], accb[8];
#pragma unroll
    for (int j = 0; j < 8; j++) {
        acca[j] = make_float4(0.f, 0.f, 0.f, 0.f);
        accb[j] = make_float4(0.f, 0.f, 0.f, 0.f);
    }

#pragma unroll
    for (int k = 0; k < 32; k++) {
        float a = xk[k];
#pragma unroll
        for (int j = 0; j < 8; j++) {
            float4 wa = sWa[k * 8 + j];
            float4 wb = sWb[k * 8 + j];
            acca[j].x += a * wa.x; acca[j].y += a * wa.y;
            acca[j].z += a * wa.z; acca[j].w += a * wa.w;
            accb[j].x += a * wb.x; accb[j].y += a * wb.y;
            accb[j].z += a * wb.z; accb[j].w += a * wb.w;
        }
    }

    float4* oar = (float4*)(oa + (size_t)r * 32);
    float4* obr = (float4*)(ob + (size_t)r * 32);
#pragma unroll
    for (int j = 0; j < 8; j++) { oar[j] = acca[j]; obr[j] = accb[j]; }
}

// ---------------------------------------------------------------------------
// Gather-aggregate: one warp per node, lane = channel.
// out[i,lane] = dis_i^2 * h[i,lane] + sum_j norm_j * h[src_j,lane] + b[lane]
// ---------------------------------------------------------------------------

__global__ __launch_bounds__(256) void k_agg(
    const float* __restrict__ h, const float* __restrict__ b,
    float* __restrict__ out, int n)
{
    int warp = (blockIdx.x * blockDim.x + threadIdx.x) >> 5;
    int lane = threadIdx.x & 31;
    if (warp >= n) return;

    int rs = g_rowstart[warp];
    int cnt = g_cnt[warp];
    float dis = g_dis[warp];

    float acc = dis * dis * h[(size_t)warp * 32 + lane];

    int j = rs, end = rs + cnt;
    for (; j + 4 <= end; j += 4) {
        int2 e0 = g_adj[j + 0];
        int2 e1 = g_adj[j + 1];
        int2 e2 = g_adj[j + 2];
        int2 e3 = g_adj[j + 3];
        float v0 = h[(size_t)e0.x * 32 + lane];
        float v1 = h[(size_t)e1.x * 32 + lane];
        float v2 = h[(size_t)e2.x * 32 + lane];
        float v3 = h[(size_t)e3.x * 32 + lane];
        acc += __int_as_float(e0.y) * v0;
        acc += __int_as_float(e1.y) * v1;
        acc += __int_as_float(e2.y) * v2;
        acc += __int_as_float(e3.y) * v3;
    }
    for (; j < end; j++) {
        int2 ev = g_adj[j];
        acc += __int_as_float(ev.y) * h[(size_t)ev.x * 32 + lane];
    }

    out[(size_t)warp * 32 + lane] = acc + b[lane];
}

// Dual aggregate for mu/logvar (shares adjacency loads)
__global__ __launch_bounds__(256) void k_agg2(
    const float* __restrict__ ha, const float* __restrict__ hb,
    const float* __restrict__ ba, const float* __restrict__ bb,
    float* __restrict__ oa, float* __restrict__ ob, int n)
{
    int warp = (blockIdx.x * blockDim.x + threadIdx.x) >> 5;
    int lane = threadIdx.x & 31;
    if (warp >= n) return;

    int rs = g_rowstart[warp];
    int cnt = g_cnt[warp];
    float dis = g_dis[warp];

    size_t self = (size_t)warp * 32 + lane;
    float acca = dis * dis * ha[self];
    float accb = dis * dis * hb[self];

    int j = rs, end = rs + cnt;
    for (; j + 4 <= end; j += 4) {
        int2 e0 = g_adj[j + 0];
        int2 e1 = g_adj[j + 1];
        int2 e2 = g_adj[j + 2];
        int2 e3 = g_adj[j + 3];
        size_t o0 = (size_t)e0.x * 32 + lane;
        size_t o1 = (size_t)e1.x * 32 + lane;
        size_t o2 = (size_t)e2.x * 32 + lane;
        size_t o3 = (size_t)e3.x * 32 + lane;
        float w0 = __int_as_float(e0.y);
        float w1 = __int_as_float(e1.y);
        float w2 = __int_as_float(e2.y);
        float w3 = __int_as_float(e3.y);
        acca += w0 * ha[o0] + w1 * ha[o1] + w2 * ha[o2] + w3 * ha[o3];
        accb += w0 * hb[o0] + w1 * hb[o1] + w2 * hb[o2] + w3 * hb[o3];
    }
    for (; j < end; j++) {
        int2 ev = g_adj[j];
        size_t o = (size_t)ev.x * 32 + lane;
        float w = __int_as_float(ev.y);
        acca += w * ha[o];
        accb += w * hb[o];
    }

    oa[self] = acca + ba[lane];
    ob[self] = accb + bb[lane];
}

// ---------------------------------------------------------------------------
// Launch
// ---------------------------------------------------------------------------

static inline int cdiv(long long a, int b) { return (int)((a + b - 1) / b); }

extern "C" void kernel_launch(void* const* d_in, const int* in_sizes, int n_in,
                              void* d_out, int out_size)
{
    const float* x   = (const float*)d_in[0];
    const void*  ei  = d_in[1];
    const float* W1  = (const float*)d_in[2];
    const float* b1  = (const float*)d_in[3];
    const float* W2  = (const float*)d_in[4];
    const float* b2  = (const float*)d_in[5];
    const float* Wmu = (const float*)d_in[6];
    const float* bmu = (const float*)d_in[7];
    const float* Wlv = (const float*)d_in[8];
    const float* blv = (const float*)d_in[9];

    int N = in_sizes[0] / 32;
    int E = in_sizes[1] / 2;

    float* mu = (float*)d_out;
    float* lv = mu + (size_t)N * 32;

    float* bufA; float* bufB; float* bufC;
    cudaGetSymbolAddress((void**)&bufA, g_bufA);
    cudaGetSymbolAddress((void**)&bufB, g_bufB);
    cudaGetSymbolAddress((void**)&bufC, g_bufC);

    const int T = 256;
    int gN = cdiv(N, T);                  // per-node
    int gE = cdiv(E, T);                  // per-edge
    int gW = cdiv((long long)N * 32, T);  // warp-per-node

    // CSR build
    k_detect<<<1, 512>>>((const int*)ei, E);
    k_zero_cnt<<<gN, T>>>(N);
    k_edge_prep<<<gE, T>>>(ei, E);
    k_rowalloc<<<gN, T>>>(N);
    k_permute<<<gE, T>>>(E);

    // Layer 1: h = x @ W1; a1 = A_hat h + b1
    k_gemm<<<gN, T>>>(x, W1, bufA, N, 0);
    k_agg<<<gW, T>>>(bufA, b1, bufB, N);

    // Layer 2: h = relu(a1) @ W2; a2 = A_hat h + b2
    k_gemm<<<gN, T>>>(bufB, W2, bufA, N, 1);
    k_agg<<<gW, T>>>(bufA, b2, bufB, N);

    // Heads: hmu = relu(a2) @ Wmu; hlv = relu(a2) @ Wlv; dual aggregate
    k_gemm2<<<gN, T>>>(bufB, Wmu, Wlv, bufA, bufC, N);
    k_agg2<<<gW, T>>>(bufA, bufC, bmu, blv, mu, lv, N);
}